// round 1
// baseline (speedup 1.0000x reference)
#include <cuda_runtime.h>
#include <math.h>

#define N_NODES 20000
#define N_EDGES 320000
#define CUTOFF 5.0f

// ---------------- device scratch (static allocation, allowed) ----------------
__device__ int   g_count[N_NODES];
__device__ int   g_cursor[N_NODES];
__device__ int   g_offset[N_NODES + 1];
// per sorted edge: Y[16] then w[32]  (48 floats, 192 B, 16B-aligned per slot)
__device__ float g_feat[(size_t)N_EDGES * 48];

// ---------------- helpers ----------------
__device__ __forceinline__ void edge_rij(const float* __restrict__ pos,
                                         const float* __restrict__ cells,
                                         const int* __restrict__ ei,
                                         const int* __restrict__ shifts,
                                         int e, int E,
                                         int& i, int& j,
                                         float& rx, float& ry, float& rz) {
    i = ei[e];
    j = ei[E + e];
    float sx = (float)shifts[3 * e + 0];
    float sy = (float)shifts[3 * e + 1];
    float sz = (float)shifts[3 * e + 2];
    rx = pos[3 * j + 0] - pos[3 * i + 0] + sx * cells[0] + sy * cells[3] + sz * cells[6];
    ry = pos[3 * j + 1] - pos[3 * i + 1] + sx * cells[1] + sy * cells[4] + sz * cells[7];
    rz = pos[3 * j + 2] - pos[3 * i + 2] + sx * cells[2] + sy * cells[5] + sz * cells[8];
}

// ---------------- kernel 0: zero counters ----------------
__global__ void zero_kernel(int N) {
    int t = blockIdx.x * blockDim.x + threadIdx.x;
    if (t < N) { g_count[t] = 0; g_cursor[t] = 0; }
}

// ---------------- kernel 1: count kept edges per node ----------------
__global__ void __launch_bounds__(256) count_kernel(
    const float* __restrict__ pos, const float* __restrict__ cells,
    const int* __restrict__ ei, const int* __restrict__ shifts, int E) {
    int e = blockIdx.x * blockDim.x + threadIdx.x;
    if (e >= E) return;
    int i, j; float rx, ry, rz;
    edge_rij(pos, cells, ei, shifts, e, E, i, j, rx, ry, rz);
    float r = sqrtf(rx * rx + ry * ry + rz * rz + 1e-12f);
    if (r < CUTOFF) atomicAdd(&g_count[i], 1);
}

// ---------------- kernel 2: exclusive scan (single block) ----------------
__global__ void __launch_bounds__(1024) scan_kernel(int N) {
    __shared__ int wsum[32];
    __shared__ int carry_s;
    int t = threadIdx.x;
    int lane = t & 31, wid = t >> 5;
    if (t == 0) carry_s = 0;
    __syncthreads();
    for (int base = 0; base < N; base += 1024) {
        int v = (base + t < N) ? g_count[base + t] : 0;
        int x = v;
        #pragma unroll
        for (int d = 1; d < 32; d <<= 1) {
            int y = __shfl_up_sync(0xffffffffu, x, d);
            if (lane >= d) x += y;
        }
        if (lane == 31) wsum[wid] = x;
        __syncthreads();
        if (wid == 0) {
            int s = wsum[lane];
            #pragma unroll
            for (int d = 1; d < 32; d <<= 1) {
                int y = __shfl_up_sync(0xffffffffu, s, d);
                if (lane >= d) s += y;
            }
            wsum[lane] = s;
        }
        __syncthreads();
        int incl = x + (wid ? wsum[wid - 1] : 0);
        int total = wsum[31];
        int carry = carry_s;
        if (base + t < N) g_offset[base + t] = carry + incl - v;
        __syncthreads();
        if (t == 0) carry_s = carry + total;
        __syncthreads();
    }
    if (t == 0) g_offset[N] = carry_s;
}

// ---------------- kernel 3: scatter per-edge features into sorted slots ----
__global__ void __launch_bounds__(256) scatter_kernel(
    const float* __restrict__ pos, const float* __restrict__ cells,
    const int* __restrict__ ei, const int* __restrict__ shifts,
    const int* __restrict__ species, const float* __restrict__ embed,
    const float* __restrict__ mu, const float* __restrict__ sigma, int E) {
    int e = blockIdx.x * blockDim.x + threadIdx.x;
    if (e >= E) return;
    int i, j; float rx, ry, rz;
    edge_rij(pos, cells, ei, shifts, e, E, i, j, rx, ry, rz);
    float r = sqrtf(rx * rx + ry * ry + rz * rz + 1e-12f);
    if (r >= CUTOFF) return;
    int slot = g_offset[i] + atomicAdd(&g_cursor[i], 1);

    float inv = 1.0f / r;
    float x = rx * inv, y = ry * inv, z = rz * inv;
    float x2 = x * x, y2 = y * y, z2 = z * z;

    float Y[16];
    Y[0]  = 0.28209479177387814f;
    Y[1]  = 0.4886025119029199f * y;
    Y[2]  = 0.4886025119029199f * z;
    Y[3]  = 0.4886025119029199f * x;
    Y[4]  = 1.0925484305920792f * x * y;
    Y[5]  = 1.0925484305920792f * y * z;
    Y[6]  = 0.31539156525252005f * (3.0f * z2 - 1.0f);
    Y[7]  = 1.0925484305920792f * x * z;
    Y[8]  = 0.5462742152960396f * (x2 - y2);
    Y[9]  = 0.5900435899266435f * y * (3.0f * x2 - y2);
    Y[10] = 2.890611442640554f * x * y * z;
    Y[11] = 0.4570457994644658f * y * (5.0f * z2 - 1.0f);
    Y[12] = 0.3731763325901154f * z * (5.0f * z2 - 3.0f);
    Y[13] = 0.4570457994644658f * x * (5.0f * z2 - 1.0f);
    Y[14] = 1.445305721320277f * z * (x2 - y2);
    Y[15] = 0.5900435899266435f * x * (x2 - 3.0f * y2);

    float fcut = 0.5f * (cosf(3.14159265358979323846f * r / CUTOFF) + 1.0f);
    float sig = sigma[0];
    float is2 = 1.0f / (2.0f * sig * sig);
    float R[8];
    #pragma unroll
    for (int n = 0; n < 8; n++) {
        float d = r - mu[n];
        R[n] = expf(-d * d * is2) * fcut;
    }
    int sp = species[j];
    float ej[4];
    #pragma unroll
    for (int p = 0; p < 4; p++) ej[p] = embed[sp * 4 + p];

    float* f = g_feat + (size_t)slot * 48;
    float4* f4 = (float4*)f;
    #pragma unroll
    for (int k = 0; k < 4; k++)
        f4[k] = make_float4(Y[4 * k], Y[4 * k + 1], Y[4 * k + 2], Y[4 * k + 3]);
    #pragma unroll
    for (int p = 0; p < 4; p++) {
        f4[4 + 2 * p]     = make_float4(ej[p] * R[0], ej[p] * R[1], ej[p] * R[2], ej[p] * R[3]);
        f4[4 + 2 * p + 1] = make_float4(ej[p] * R[4], ej[p] * R[5], ej[p] * R[6], ej[p] * R[7]);
    }
}

// ---------------- kernel 4: per-node accumulate + power spectrum ------------
__global__ void __launch_bounds__(256) node_kernel(float* __restrict__ out, int N) {
    __shared__ float sc[8][512];
    int lane = threadIdx.x & 31;
    int w = threadIdx.x >> 5;
    int n = blockIdx.x * 8 + w;
    if (n >= N) return;

    float c[16];
    #pragma unroll
    for (int m = 0; m < 16; m++) c[m] = 0.0f;

    int s = g_offset[n], e = g_offset[n + 1];
    for (int k = s; k < e; k++) {
        const float* f = g_feat + (size_t)k * 48;
        float yv = f[lane & 15];     // lanes 0..15 hold Y[0..15]
        float wv = f[16 + lane];     // lane q holds w[q]
        #pragma unroll
        for (int m = 0; m < 16; m++)
            c[m] = fmaf(__shfl_sync(0xffffffffu, yv, m), wv, c[m]);
    }

    #pragma unroll
    for (int m = 0; m < 16; m++) sc[w][m * 32 + lane] = c[m];
    __syncwarp();

    float* o = out + (size_t)n * 4096 + lane;
    const float cg1 = 0.57735026918962576f;   // 1/sqrt(3)
    const float cg2 = 0.44721359549995793f;   // 1/sqrt(5)
    const float cg3 = 0.37796447300922722f;   // 1/sqrt(7)
    #pragma unroll 4
    for (int q = 0; q < 32; q++) {
        const float* sq = &sc[w][q];
        float a0 = sq[0] * c[0];
        float a1 = sq[32] * c[1];
        a1 = fmaf(sq[64], c[2], a1);
        a1 = fmaf(sq[96], c[3], a1);
        float a2 = sq[128] * c[4];
        a2 = fmaf(sq[160], c[5], a2);
        a2 = fmaf(sq[192], c[6], a2);
        a2 = fmaf(sq[224], c[7], a2);
        a2 = fmaf(sq[256], c[8], a2);
        float a3 = sq[288] * c[9];
        a3 = fmaf(sq[320], c[10], a3);
        a3 = fmaf(sq[352], c[11], a3);
        a3 = fmaf(sq[384], c[12], a3);
        a3 = fmaf(sq[416], c[13], a3);
        a3 = fmaf(sq[448], c[14], a3);
        a3 = fmaf(sq[480], c[15], a3);
        o[q * 32]          = a0;        // cg0 = 1
        o[1024 + q * 32]   = cg1 * a1;
        o[2048 + q * 32]   = cg2 * a2;
        o[3072 + q * 32]   = cg3 * a3;
    }
}

// ---------------- launch ----------------
extern "C" void kernel_launch(void* const* d_in, const int* in_sizes, int n_in,
                              void* d_out, int out_size) {
    const float* pos     = (const float*)d_in[0];
    const float* cells   = (const float*)d_in[1];
    const int*   species = (const int*)d_in[2];
    const int*   ei      = (const int*)d_in[3];
    const int*   shifts  = (const int*)d_in[4];
    const float* embed   = (const float*)d_in[5];
    const float* mu      = (const float*)d_in[6];
    const float* sigma   = (const float*)d_in[7];
    int N = in_sizes[0] / 3;
    int E = in_sizes[3] / 2;
    float* out = (float*)d_out;

    zero_kernel<<<(N + 255) / 256, 256>>>(N);
    count_kernel<<<(E + 255) / 256, 256>>>(pos, cells, ei, shifts, E);
    scan_kernel<<<1, 1024>>>(N);
    scatter_kernel<<<(E + 255) / 256, 256>>>(pos, cells, ei, shifts, species,
                                             embed, mu, sigma, E);
    node_kernel<<<(N + 7) / 8, 256>>>(out, N);
}

// round 2
// speedup vs baseline: 1.0694x; 1.0694x over previous
#include <cuda_runtime.h>
#include <math.h>

#define N_NODES 20000
#define N_EDGES 320000
#define CUTOFF 5.0f

// ---------------- device scratch ----------------
__device__ int   g_count[N_NODES];
__device__ int   g_offset[N_NODES + 1];
__device__ int   g_rank[N_EDGES];
// per sorted edge: [Y0..15][R0..7][ej0..3][pad4]  (32 floats, 128 B aligned)
__device__ __align__(128) float g_feat[(size_t)N_EDGES * 32];

// ---------------- helpers ----------------
__device__ __forceinline__ void edge_rij(const float* __restrict__ pos,
                                         const float* __restrict__ cells,
                                         const int* __restrict__ ei,
                                         const int* __restrict__ shifts,
                                         int e, int E,
                                         int& i, int& j,
                                         float& rx, float& ry, float& rz) {
    i = ei[e];
    j = ei[E + e];
    float sx = (float)shifts[3 * e + 0];
    float sy = (float)shifts[3 * e + 1];
    float sz = (float)shifts[3 * e + 2];
    rx = pos[3 * j + 0] - pos[3 * i + 0] + sx * cells[0] + sy * cells[3] + sz * cells[6];
    ry = pos[3 * j + 1] - pos[3 * i + 1] + sx * cells[1] + sy * cells[4] + sz * cells[7];
    rz = pos[3 * j + 2] - pos[3 * i + 2] + sx * cells[2] + sy * cells[5] + sz * cells[8];
}

// ---------------- kernel 0: zero counters ----------------
__global__ void zero_kernel(int N) {
    int t = blockIdx.x * blockDim.x + threadIdx.x;
    if (t < N) g_count[t] = 0;
}

// ---------------- kernel 1: count + assign rank ----------------
__global__ void __launch_bounds__(256) count_kernel(
    const float* __restrict__ pos, const float* __restrict__ cells,
    const int* __restrict__ ei, const int* __restrict__ shifts, int E) {
    int e = blockIdx.x * blockDim.x + threadIdx.x;
    if (e >= E) return;
    int i, j; float rx, ry, rz;
    edge_rij(pos, cells, ei, shifts, e, E, i, j, rx, ry, rz);
    float r2 = rx * rx + ry * ry + rz * rz + 1e-12f;
    int rk = -1;
    if (r2 < CUTOFF * CUTOFF) rk = atomicAdd(&g_count[i], 1);
    g_rank[e] = rk;
}

// ---------------- kernel 2: exclusive scan, serial chunks, 2 syncs ----------
__global__ void __launch_bounds__(1024) scan_kernel(int N) {
    __shared__ int part[1024];
    __shared__ int wsum[32];
    int t = threadIdx.x, lane = t & 31, wid = t >> 5;
    int chunk = (N + 1023) >> 10;
    int s = t * chunk;
    int e = s + chunk; if (e > N) e = N;
    int sum = 0;
    for (int k = s; k < e; k++) sum += g_count[k];
    // scan the 1024 partials
    int x = sum;
    #pragma unroll
    for (int d = 1; d < 32; d <<= 1) {
        int y = __shfl_up_sync(0xffffffffu, x, d);
        if (lane >= d) x += y;
    }
    if (lane == 31) wsum[wid] = x;
    __syncthreads();
    if (wid == 0) {
        int v = wsum[lane];
        #pragma unroll
        for (int d = 1; d < 32; d <<= 1) {
            int y = __shfl_up_sync(0xffffffffu, v, d);
            if (lane >= d) v += y;
        }
        wsum[lane] = v;
    }
    __syncthreads();
    int excl = x - sum + (wid ? wsum[wid - 1] : 0);
    for (int k = s; k < e; k++) {
        g_offset[k] = excl;
        excl += g_count[k];
    }
    if (e == N && s < N) g_offset[N] = excl;
}

// ---------------- kernel 3: scatter per-edge features (no atomics) ---------
__global__ void __launch_bounds__(256) scatter_kernel(
    const float* __restrict__ pos, const float* __restrict__ cells,
    const int* __restrict__ ei, const int* __restrict__ shifts,
    const int* __restrict__ species, const float* __restrict__ embed,
    const float* __restrict__ mu, const float* __restrict__ sigma, int E) {
    int e = blockIdx.x * blockDim.x + threadIdx.x;
    if (e >= E) return;
    int rk = g_rank[e];
    if (rk < 0) return;
    int i, j; float rx, ry, rz;
    edge_rij(pos, cells, ei, shifts, e, E, i, j, rx, ry, rz);
    float r = sqrtf(rx * rx + ry * ry + rz * rz + 1e-12f);
    int slot = g_offset[i] + rk;

    float inv = 1.0f / r;
    float x = rx * inv, y = ry * inv, z = rz * inv;
    float x2 = x * x, y2 = y * y, z2 = z * z;

    float Y[16];
    Y[0]  = 0.28209479177387814f;
    Y[1]  = 0.4886025119029199f * y;
    Y[2]  = 0.4886025119029199f * z;
    Y[3]  = 0.4886025119029199f * x;
    Y[4]  = 1.0925484305920792f * x * y;
    Y[5]  = 1.0925484305920792f * y * z;
    Y[6]  = 0.31539156525252005f * (3.0f * z2 - 1.0f);
    Y[7]  = 1.0925484305920792f * x * z;
    Y[8]  = 0.5462742152960396f * (x2 - y2);
    Y[9]  = 0.5900435899266435f * y * (3.0f * x2 - y2);
    Y[10] = 2.890611442640554f * x * y * z;
    Y[11] = 0.4570457994644658f * y * (5.0f * z2 - 1.0f);
    Y[12] = 0.3731763325901154f * z * (5.0f * z2 - 3.0f);
    Y[13] = 0.4570457994644658f * x * (5.0f * z2 - 1.0f);
    Y[14] = 1.445305721320277f * z * (x2 - y2);
    Y[15] = 0.5900435899266435f * x * (x2 - 3.0f * y2);

    float fcut = 0.5f * (cosf(3.14159265358979323846f * r / CUTOFF) + 1.0f);
    float sig = sigma[0];
    float is2 = 1.0f / (2.0f * sig * sig);
    float R[8];
    #pragma unroll
    for (int n = 0; n < 8; n++) {
        float d = r - mu[n];
        R[n] = expf(-d * d * is2) * fcut;
    }
    int sp = species[j];

    float4* f4 = (float4*)(g_feat + (size_t)slot * 32);
    #pragma unroll
    for (int k = 0; k < 4; k++)
        f4[k] = make_float4(Y[4 * k], Y[4 * k + 1], Y[4 * k + 2], Y[4 * k + 3]);
    f4[4] = make_float4(R[0], R[1], R[2], R[3]);
    f4[5] = make_float4(R[4], R[5], R[6], R[7]);
    f4[6] = *(const float4*)(embed + sp * 4);
    // f4[7] is padding — never read, never written
}

// ---------------- kernel 4: per-node accumulate + power spectrum ------------
__global__ void __launch_bounds__(256) node_kernel(float* __restrict__ out, int N) {
    __shared__ float sc[8][512];
    int lane = threadIdx.x & 31;
    int w = threadIdx.x >> 5;
    int n = blockIdx.x * 8 + w;
    if (n >= N) return;

    float c[16];
    #pragma unroll
    for (int m = 0; m < 16; m++) c[m] = 0.0f;

    int s = g_offset[n], e = g_offset[n + 1];
    int iy = lane & 15, ir = 16 + (lane & 7), ie = 24 + (lane >> 3);

    int k = s;
    for (; k + 1 < e; k += 2) {
        const float* f0 = g_feat + (size_t)k * 32;
        const float* f1 = f0 + 32;
        float y0 = f0[iy], r0 = f0[ir], e0 = f0[ie];
        float y1 = f1[iy], r1 = f1[ir], e1 = f1[ie];
        float w0 = r0 * e0;
        float w1 = r1 * e1;
        #pragma unroll
        for (int m = 0; m < 16; m++)
            c[m] = fmaf(__shfl_sync(0xffffffffu, y0, m), w0, c[m]);
        #pragma unroll
        for (int m = 0; m < 16; m++)
            c[m] = fmaf(__shfl_sync(0xffffffffu, y1, m), w1, c[m]);
    }
    if (k < e) {
        const float* f0 = g_feat + (size_t)k * 32;
        float y0 = f0[iy], r0 = f0[ir], e0 = f0[ie];
        float w0 = r0 * e0;
        #pragma unroll
        for (int m = 0; m < 16; m++)
            c[m] = fmaf(__shfl_sync(0xffffffffu, y0, m), w0, c[m]);
    }

    float* scw = sc[w];
    #pragma unroll
    for (int m = 0; m < 16; m++) scw[m * 32 + lane] = c[m];
    __syncwarp();

    const float cg1 = 0.57735026918962576f;   // 1/sqrt(3)
    const float cg2 = 0.44721359549995793f;   // 1/sqrt(5)
    const float cg3 = 0.37796447300922722f;   // 1/sqrt(7)
    int qg = lane >> 3;            // 0..3
    int rb = (lane & 7) * 4;       // 0,4,...,28
    float* ob = out + (size_t)n * 4096;

    #pragma unroll
    for (int it = 0; it < 8; it++) {
        int q = it * 4 + qg;
        float4 a0 = make_float4(0.f, 0.f, 0.f, 0.f);
        float4 a1 = a0, a2 = a0, a3 = a0;
        #pragma unroll
        for (int m = 0; m < 16; m++) {
            float cq = scw[m * 32 + q];
            float4 cr = *(const float4*)&scw[m * 32 + rb];
            float4& acc = (m == 0) ? a0 : (m < 4) ? a1 : (m < 9) ? a2 : a3;
            acc.x = fmaf(cq, cr.x, acc.x);
            acc.y = fmaf(cq, cr.y, acc.y);
            acc.z = fmaf(cq, cr.z, acc.z);
            acc.w = fmaf(cq, cr.w, acc.w);
        }
        a1.x *= cg1; a1.y *= cg1; a1.z *= cg1; a1.w *= cg1;
        a2.x *= cg2; a2.y *= cg2; a2.z *= cg2; a2.w *= cg2;
        a3.x *= cg3; a3.y *= cg3; a3.z *= cg3; a3.w *= cg3;
        int base = q * 32 + rb;
        *(float4*)(ob + base)        = a0;
        *(float4*)(ob + 1024 + base) = a1;
        *(float4*)(ob + 2048 + base) = a2;
        *(float4*)(ob + 3072 + base) = a3;
    }
}

// ---------------- launch ----------------
extern "C" void kernel_launch(void* const* d_in, const int* in_sizes, int n_in,
                              void* d_out, int out_size) {
    const float* pos     = (const float*)d_in[0];
    const float* cells   = (const float*)d_in[1];
    const int*   species = (const int*)d_in[2];
    const int*   ei      = (const int*)d_in[3];
    const int*   shifts  = (const int*)d_in[4];
    const float* embed   = (const float*)d_in[5];
    const float* mu      = (const float*)d_in[6];
    const float* sigma   = (const float*)d_in[7];
    int N = in_sizes[0] / 3;
    int E = in_sizes[3] / 2;
    float* out = (float*)d_out;

    zero_kernel<<<(N + 255) / 256, 256>>>(N);
    count_kernel<<<(E + 255) / 256, 256>>>(pos, cells, ei, shifts, E);
    scan_kernel<<<1, 1024>>>(N);
    scatter_kernel<<<(E + 255) / 256, 256>>>(pos, cells, ei, shifts, species,
                                             embed, mu, sigma, E);
    node_kernel<<<(N + 7) / 8, 256>>>(out, N);
}